// round 10
// baseline (speedup 1.0000x reference)
#include <cuda_runtime.h>
#include <cuda_bf16.h>
#include <cstddef>
#include <cstdint>

#define BQ 8192
#define NQ 784
#define NSITES 782
#define NSTEP 391          // steps per half-chain
#define RING 4             // smem stages per warp
#define DIST 3             // prefetch distance (sites ahead)

typedef unsigned long long ull;

// Scratch
__device__ float2     g_feat[(size_t)NQ * BQ];         // [site][batch] (cos,sin)
__device__ ulonglong2 g_coresT[(size_t)NSITES * 50];   // transposed cores (backward)
__device__ ull        g_V[(size_t)BQ * 5];
__device__ ull        g_U[(size_t)BQ * 5];

// ---------------- packed f32x2 helpers ----------------
__device__ __forceinline__ ull pack2(float lo, float hi) {
    ull r;
    asm("mov.b64 %0, {%1, %2};" : "=l"(r)
        : "r"(__float_as_uint(lo)), "r"(__float_as_uint(hi)));
    return r;
}
__device__ __forceinline__ float2 unpack2(ull v) {
    unsigned int lo, hi;
    asm("mov.b64 {%0, %1}, %2;" : "=r"(lo), "=r"(hi) : "l"(v));
    return make_float2(__uint_as_float(lo), __uint_as_float(hi));
}
__device__ __forceinline__ ull fma2(ull a, ull b, ull c) {
    ull d;
    asm("fma.rn.f32x2 %0, %1, %2, %3;" : "=l"(d) : "l"(a), "l"(b), "l"(c));
    return d;
}
__device__ __forceinline__ ull mul2(ull a, ull b) {
    ull d;
    asm("mul.rn.f32x2 %0, %1, %2;" : "=l"(d) : "l"(a), "l"(b));
    return d;
}

// ---------------- cp.async helpers ----------------
__device__ __forceinline__ void cp16(uint32_t saddr, const void* gptr) {
    asm volatile("cp.async.cg.shared.global [%0], [%1], 16;"
                 :: "r"(saddr), "l"(gptr) : "memory");
}
__device__ __forceinline__ void cp_commit() {
    asm volatile("cp.async.commit_group;" ::: "memory");
}
template <int N> __device__ __forceinline__ void cp_wait() {
    asm volatile("cp.async.wait_group %0;" :: "n"(N) : "memory");
}

// ---------------------------------------------------------------------------
// K1: featurize + transpose. x:(B,N) -> g_feat:(N,B) float2 (cos, sin)
// ---------------------------------------------------------------------------
__global__ void feat_kernel(const float* __restrict__ x) {
    __shared__ float2 tf[32][33];
    const int tx = threadIdx.x;
    const int ty = threadIdx.y;
    const int n0 = blockIdx.x * 32;
    const int b0 = blockIdx.y * 32;

    #pragma unroll
    for (int j = 0; j < 32; j += 8) {
        int n = n0 + tx;
        int b = b0 + ty + j;
        if (n < NQ) {
            float val = x[(size_t)b * NQ + n];
            float s, c;
            sincospif(val, &s, &c);
            tf[tx][ty + j] = make_float2(c, s);
        }
    }
    __syncthreads();
    #pragma unroll
    for (int j = 0; j < 32; j += 8) {
        int n = n0 + ty + j;
        int b = b0 + tx;
        if (n < NQ) g_feat[(size_t)n * BQ + b] = tf[ty + j][tx];
    }
}

// ---------------------------------------------------------------------------
// K1b: transpose cores for the backward half: src[i][l][d][r] -> dst[i][r][d][l]
// ---------------------------------------------------------------------------
__global__ void transpose_cores(const float* __restrict__ src) {
    const int site = blockIdx.x;
    const int o = threadIdx.x;          // 0..199 : o = r*20 + d*10 + l
    const int r = o / 20;
    const int d = (o % 20) / 10;
    const int l = o % 10;
    ((float*)g_coresT)[(size_t)site * 200 + o] =
        src[(size_t)site * 200 + l * 20 + d * 10 + r];
}

// ---------------------------------------------------------------------------
// K2: TWO chains per thread (same direction -> shared matrix stream).
// grid=128, block=64 (2 warps). Blocks [0,64): forward; [64,128): backward.
// Block i covers 128 chain-halves: thread t owns b = i*128+t and i*128+64+t.
// Warp-private cp.async smem ring staging, exactly the R5 idioms.
// ---------------------------------------------------------------------------
__global__ __launch_bounds__(64, 1)
void chain_kernel(const float* __restrict__ core_first,
                  const float* __restrict__ cores_mid,
                  const float* __restrict__ core_last) {
    __shared__ __align__(16) char smem[2][RING][800];

    const int tid  = threadIdx.x;
    const int wid  = tid >> 5;
    const int lane = tid & 31;
    const bool fwd = (blockIdx.x < 64);
    const int base = (fwd ? blockIdx.x : blockIdx.x - 64) * 128;
    const int bA = base + tid;
    const int bB = base + 64 + tid;

    const char* gsrc;
    long gstep;
    long foff0;          // element offset of first in-loop feature site (row)
    long fstep;
    if (fwd) {
        gsrc  = (const char*)cores_mid;                      // site 0 ascending
        gstep = 800;
        foff0 = (long)BQ;                                    // feature site 1
        fstep = BQ;
    } else {
        gsrc  = (const char*)(g_coresT + (size_t)(NSITES - 1) * 50); // site 781 desc
        gstep = -800;
        foff0 = (long)(NQ - 2) * BQ;                         // feature site 782
        fstep = -(long)BQ;
    }
    const float2* fpA = g_feat + foff0 + bA;
    const float2* fpB = g_feat + foff0 + bB;

    const uint32_t sbase = (uint32_t)__cvta_generic_to_shared(&smem[wid][0][0]);

    // prologue: stage sites 0..DIST-1
    #pragma unroll
    for (int s = 0; s < DIST; s++) {
        const char* g = gsrc + (long)s * gstep;
        uint32_t dst = sbase + s * 800;
        cp16(dst + lane * 16, g + lane * 16);
        if (lane < 18) cp16(dst + (32 + lane) * 16, g + (32 + lane) * 16);
        cp_commit();
    }

    // init state for both chains
    ull vpA[5], vpB[5];
    if (fwd) {
        const float2 fA = g_feat[bA];
        const float2 fB = g_feat[bB];
        const ull* cfc = (const ull*)core_first;
        const ull* cfs = (const ull*)(core_first + 10);
        const ull cA = pack2(fA.x, fA.x), sA = pack2(fA.y, fA.y);
        const ull cB = pack2(fB.x, fB.x), sB = pack2(fB.y, fB.y);
        #pragma unroll
        for (int j = 0; j < 5; j++) {
            const ull qc = __ldg(cfc + j), qs = __ldg(cfs + j);
            vpA[j] = fma2(sA, qs, mul2(cA, qc));
            vpB[j] = fma2(sB, qs, mul2(cB, qc));
        }
    } else {
        const float2 fA = g_feat[(size_t)(NQ - 1) * BQ + bA];
        const float2 fB = g_feat[(size_t)(NQ - 1) * BQ + bB];
        const float2* cl = (const float2*)core_last;
        #pragma unroll
        for (int j = 0; j < 5; j++) {
            float2 qa = __ldg(cl + 2 * j);
            float2 qb = __ldg(cl + 2 * j + 1);
            vpA[j] = pack2(fA.x * qa.x + fA.y * qa.y, fA.x * qb.x + fA.y * qb.y);
            vpB[j] = pack2(fB.x * qa.x + fB.y * qa.y, fB.x * qb.x + fB.y * qb.y);
        }
    }

    float2 fcA = *fpA;
    float2 fcB = *fpB;

    for (int k = 0; k < NSTEP; k++) {
        cp_wait<DIST - 1>();          // site k staged
        __syncwarp();

        const float2 fnA = fpA[(long)(k + 1) * fstep];
        const float2 fnB = fpB[(long)(k + 1) * fstep];

        const ulonglong2* row = (const ulonglong2*)&smem[wid][k & (RING - 1)][0];

        float2 uA0 = unpack2(vpA[0]), uA1 = unpack2(vpA[1]), uA2 = unpack2(vpA[2]),
               uA3 = unpack2(vpA[3]), uA4 = unpack2(vpA[4]);
        float2 uB0 = unpack2(vpB[0]), uB1 = unpack2(vpB[1]), uB2 = unpack2(vpB[2]),
               uB3 = unpack2(vpB[3]), uB4 = unpack2(vpB[4]);

        ull aA0, aA1, aA2, aA3, aA4, cA0, cA1, cA2, cA3, cA4;
        ull aB0, aB1, aB2, aB3, aB4, cB0, cB1, cB2, cB3, cB4;

        #pragma unroll
        for (int l = 0; l < 10; l++) {
            const ulonglong2 p0 = row[l * 5 + 0];
            const ulonglong2 p1 = row[l * 5 + 1];
            const ulonglong2 p2 = row[l * 5 + 2];
            const ulonglong2 p3 = row[l * 5 + 3];
            const ulonglong2 p4 = row[l * 5 + 4];
            float vA, vB;
            switch (l) {
                case 0: vA = uA0.x; vB = uB0.x; break;
                case 1: vA = uA0.y; vB = uB0.y; break;
                case 2: vA = uA1.x; vB = uB1.x; break;
                case 3: vA = uA1.y; vB = uB1.y; break;
                case 4: vA = uA2.x; vB = uB2.x; break;
                case 5: vA = uA2.y; vB = uB2.y; break;
                case 6: vA = uA3.x; vB = uB3.x; break;
                case 7: vA = uA3.y; vB = uB3.y; break;
                case 8: vA = uA4.x; vB = uB4.x; break;
                default: vA = uA4.y; vB = uB4.y; break;
            }
            const ull vA2 = pack2(vA, vA);
            const ull vB2 = pack2(vB, vB);
            if (l == 0) {
                aA0 = mul2(vA2, p0.x); aA1 = mul2(vA2, p0.y);
                aA2 = mul2(vA2, p1.x); aA3 = mul2(vA2, p1.y);
                aA4 = mul2(vA2, p2.x);
                cA0 = mul2(vA2, p2.y);
                cA1 = mul2(vA2, p3.x); cA2 = mul2(vA2, p3.y);
                cA3 = mul2(vA2, p4.x); cA4 = mul2(vA2, p4.y);
                aB0 = mul2(vB2, p0.x); aB1 = mul2(vB2, p0.y);
                aB2 = mul2(vB2, p1.x); aB3 = mul2(vB2, p1.y);
                aB4 = mul2(vB2, p2.x);
                cB0 = mul2(vB2, p2.y);
                cB1 = mul2(vB2, p3.x); cB2 = mul2(vB2, p3.y);
                cB3 = mul2(vB2, p4.x); cB4 = mul2(vB2, p4.y);
            } else {
                aA0 = fma2(vA2, p0.x, aA0); aA1 = fma2(vA2, p0.y, aA1);
                aA2 = fma2(vA2, p1.x, aA2); aA3 = fma2(vA2, p1.y, aA3);
                aA4 = fma2(vA2, p2.x, aA4);
                cA0 = fma2(vA2, p2.y, cA0);
                cA1 = fma2(vA2, p3.x, cA1); cA2 = fma2(vA2, p3.y, cA2);
                cA3 = fma2(vA2, p4.x, cA3); cA4 = fma2(vA2, p4.y, cA4);
                aB0 = fma2(vB2, p0.x, aB0); aB1 = fma2(vB2, p0.y, aB1);
                aB2 = fma2(vB2, p1.x, aB2); aB3 = fma2(vB2, p1.y, aB3);
                aB4 = fma2(vB2, p2.x, aB4);
                cB0 = fma2(vB2, p2.y, cB0);
                cB1 = fma2(vB2, p3.x, cB1); cB2 = fma2(vB2, p3.y, cB2);
                cB3 = fma2(vB2, p4.x, cB3); cB4 = fma2(vB2, p4.y, cB4);
            }
        }
        {
            const ull fc2 = pack2(fcA.x, fcA.x);
            const ull fs2 = pack2(fcA.y, fcA.y);
            vpA[0] = fma2(fs2, cA0, mul2(fc2, aA0));
            vpA[1] = fma2(fs2, cA1, mul2(fc2, aA1));
            vpA[2] = fma2(fs2, cA2, mul2(fc2, aA2));
            vpA[3] = fma2(fs2, cA3, mul2(fc2, aA3));
            vpA[4] = fma2(fs2, cA4, mul2(fc2, aA4));
        }
        {
            const ull fc2 = pack2(fcB.x, fcB.x);
            const ull fs2 = pack2(fcB.y, fcB.y);
            vpB[0] = fma2(fs2, cB0, mul2(fc2, aB0));
            vpB[1] = fma2(fs2, cB1, mul2(fc2, aB1));
            vpB[2] = fma2(fs2, cB2, mul2(fc2, aB2));
            vpB[3] = fma2(fs2, cB3, mul2(fc2, aB3));
            vpB[4] = fma2(fs2, cB4, mul2(fc2, aB4));
        }
        fcA = fnA;
        fcB = fnB;

        // stage site k+DIST (R5 order: after compute)
        if (k + DIST < NSTEP) {
            const char* g = gsrc + (long)(k + DIST) * gstep;
            uint32_t dst = sbase + ((k + DIST) & (RING - 1)) * 800;
            cp16(dst + lane * 16, g + lane * 16);
            if (lane < 18) cp16(dst + (32 + lane) * 16, g + (32 + lane) * 16);
        }
        cp_commit();
    }

    if (fwd) {
        #pragma unroll
        for (int j = 0; j < 5; j++) {
            g_V[(size_t)bA * 5 + j] = vpA[j];
            g_V[(size_t)bB * 5 + j] = vpB[j];
        }
    } else {
        #pragma unroll
        for (int j = 0; j < 5; j++) {
            g_U[(size_t)bA * 5 + j] = vpA[j];
            g_U[(size_t)bB * 5 + j] = vpB[j];
        }
    }
}

// ---------------------------------------------------------------------------
// K3: s[b] = dot(v,u);  logits[b,c] = s[b] * w[c],  w[c] = sum_d OT[c,d,0]
// ---------------------------------------------------------------------------
__global__ void combine_kernel(const float* __restrict__ ot,
                               float* __restrict__ out) {
    __shared__ float ws[10];
    const int tid = threadIdx.x;
    if (tid < 10) {
        float w = 0.f;
        #pragma unroll
        for (int d = 0; d < 10; d++) w += ot[tid * 10 + d];
        ws[tid] = w;
    }
    __syncthreads();

    const int b = blockIdx.x * blockDim.x + tid;
    if (b >= BQ) return;
    float s = 0.f;
    #pragma unroll
    for (int j = 0; j < 5; j++) {
        float2 a = unpack2(g_V[(size_t)b * 5 + j]);
        float2 u = unpack2(g_U[(size_t)b * 5 + j]);
        s += a.x * u.x + a.y * u.y;
    }
    #pragma unroll
    for (int c = 0; c < 10; c++)
        out[(size_t)b * 10 + c] = s * ws[c];
}

// ---------------------------------------------------------------------------
extern "C" void kernel_launch(void* const* d_in, const int* in_sizes, int n_in,
                              void* d_out, int out_size) {
    const float* x          = (const float*)d_in[0];  // (8192, 784)
    const float* core_first = (const float*)d_in[1];  // (1, 2, 10)
    const float* cores_mid  = (const float*)d_in[2];  // (782, 10, 2, 10)
    const float* core_last  = (const float*)d_in[3];  // (10, 2, 1)
    const float* out_t      = (const float*)d_in[4];  // (10, 10, 1)
    float* out = (float*)d_out;                       // (8192, 10)

    dim3 fgrid((NQ + 31) / 32, BQ / 32);
    dim3 fblk(32, 8);
    feat_kernel<<<fgrid, fblk>>>(x);
    transpose_cores<<<NSITES, 200>>>(cores_mid);

    chain_kernel<<<128, 64>>>(core_first, cores_mid, core_last);

    combine_kernel<<<BQ / 256, 256>>>(out_t, out);
}

// round 11
// speedup vs baseline: 1.0492x; 1.0492x over previous
#include <cuda_runtime.h>
#include <cuda_bf16.h>
#include <cstddef>
#include <cstdint>

#define BQ 8192
#define NQ 784
#define NSITES 782
#define NSTEP 391          // steps per half-chain
#define RING 4             // smem stages per warp
#define DIST 3             // prefetch distance (sites ahead)

typedef unsigned long long ull;

// Scratch
__device__ float2     g_feat[(size_t)NQ * BQ];          // [site][batch] (cos,sin)
__device__ ulonglong2 g_packDF[(size_t)NSITES * 50];    // fwd, d-split chunk layout
__device__ ulonglong2 g_packDR[(size_t)NSITES * 50];    // bwd (transposed), d-split
__device__ ull        g_V[(size_t)BQ * 5];
__device__ ull        g_U[(size_t)BQ * 5];

// ---------------- packed f32x2 helpers ----------------
__device__ __forceinline__ ull pack2(float lo, float hi) {
    ull r;
    asm("mov.b64 %0, {%1, %2};" : "=l"(r)
        : "r"(__float_as_uint(lo)), "r"(__float_as_uint(hi)));
    return r;
}
__device__ __forceinline__ float2 unpack2(ull v) {
    unsigned int lo, hi;
    asm("mov.b64 {%0, %1}, %2;" : "=r"(lo), "=r"(hi) : "l"(v));
    return make_float2(__uint_as_float(lo), __uint_as_float(hi));
}
__device__ __forceinline__ ull fma2(ull a, ull b, ull c) {
    ull d;
    asm("fma.rn.f32x2 %0, %1, %2, %3;" : "=l"(d) : "l"(a), "l"(b), "l"(c));
    return d;
}
__device__ __forceinline__ ull mul2(ull a, ull b) {
    ull d;
    asm("mul.rn.f32x2 %0, %1, %2;" : "=l"(d) : "l"(a), "l"(b));
    return d;
}
__device__ __forceinline__ ull add2(ull a, ull b) {
    ull d;
    asm("add.rn.f32x2 %0, %1, %2;" : "=l"(d) : "l"(a), "l"(b));
    return d;
}

// ---------------- cp.async helpers ----------------
__device__ __forceinline__ void cp16(uint32_t saddr, const void* gptr) {
    asm volatile("cp.async.cg.shared.global [%0], [%1], 16;"
                 :: "r"(saddr), "l"(gptr) : "memory");
}
__device__ __forceinline__ void cp_commit() {
    asm volatile("cp.async.commit_group;" ::: "memory");
}
template <int N> __device__ __forceinline__ void cp_wait() {
    asm volatile("cp.async.wait_group %0;" :: "n"(N) : "memory");
}

// ---------------------------------------------------------------------------
// K1: featurize + transpose. x:(B,N) -> g_feat:(N,B) float2 (cos, sin)
// ---------------------------------------------------------------------------
__global__ void feat_kernel(const float* __restrict__ x) {
    __shared__ float2 tf[32][33];
    const int tx = threadIdx.x;
    const int ty = threadIdx.y;
    const int n0 = blockIdx.x * 32;
    const int b0 = blockIdx.y * 32;

    #pragma unroll
    for (int j = 0; j < 32; j += 8) {
        int n = n0 + tx;
        int b = b0 + ty + j;
        if (n < NQ) {
            float val = x[(size_t)b * NQ + n];
            float s, c;
            sincospif(val, &s, &c);
            tf[tx][ty + j] = make_float2(c, s);
        }
    }
    __syncthreads();
    #pragma unroll
    for (int j = 0; j < 32; j += 8) {
        int n = n0 + ty + j;
        int b = b0 + tx;
        if (n < NQ) g_feat[(size_t)n * BQ + b] = tf[ty + j][tx];
    }
}

// ---------------------------------------------------------------------------
// K1b: repack cores into d-split chunk layout.
// src[site][l][d][r] (200 floats). Output per site: [d=0 block 400B][d=1 400B].
// Within a block: chunk(j, lp) = 16B, floats k=0..3 with
//   in  = 2*lp + (k>>1), out = 2*j + (k&1)
//   fwd:  val = src[in*20 + d*10 + out]   (out-index = r, column accumulation)
//   bwd:  val = src[out*20 + d*10 + in]   (transposed)
// ---------------------------------------------------------------------------
__global__ void prep_kernel(const float* __restrict__ src) {
    const int site = blockIdx.x;
    const int o = threadIdx.x;              // 0..199
    const int d  = o / 100;
    const int rem = o % 100;
    const int j  = rem / 20;
    const int lp = (rem % 20) / 4;
    const int k  = rem % 4;
    const int in  = 2 * lp + (k >> 1);
    const int out = 2 * j + (k & 1);
    const float* s = src + (size_t)site * 200;
    ((float*)g_packDF)[(size_t)site * 200 + o] = s[in * 20 + d * 10 + out];
    ((float*)g_packDR)[(size_t)site * 200 + o] = s[out * 20 + d * 10 + in];
}

// ---------------------------------------------------------------------------
// K2: d-split chain. 2 threads per chain-half: lane<16 computes the cos-matrix
// half (A^T v or A u), lane>=16 the sin half; each scales by its coefficient,
// shfl.bfly(16) exchanges, add -> both lanes hold identical v_new.
// block=256 (8 warps -> 2 warps/SMSP), grid=128: blocks [0,64) fwd, [64,128) bwd.
// Warp handles 16 chains (lane&15). Warp-private cp.async smem ring (R5 idiom).
// ---------------------------------------------------------------------------
__global__ __launch_bounds__(256, 1)
void chain_kernel(const float* __restrict__ core_first,
                  const float* __restrict__ core_last) {
    __shared__ __align__(16) char smem[8][RING][800];

    const int tid  = threadIdx.x;
    const int wid  = tid >> 5;
    const int lane = tid & 31;
    const int half = lane >> 4;             // 0: cos half, 1: sin half
    const int cid  = lane & 15;
    const bool fwd = (blockIdx.x < 64);
    const int b = (fwd ? blockIdx.x : blockIdx.x - 64) * 128 + wid * 16 + cid;

    const char* gsrc;
    long gstep;
    long foff0;
    long fstep;
    if (fwd) {
        gsrc  = (const char*)g_packDF;                         // site 0 ascending
        gstep = 800;
        foff0 = (long)BQ;                                      // feature site 1
        fstep = BQ;
    } else {
        gsrc  = (const char*)(g_packDR + (size_t)(NSITES - 1) * 50); // site 781 desc
        gstep = -800;
        foff0 = (long)(NQ - 2) * BQ;                           // feature site 782
        fstep = -(long)BQ;
    }
    const float2* fp = g_feat + foff0 + b;

    const uint32_t sbase = (uint32_t)__cvta_generic_to_shared(&smem[wid][0][0]);

    // prologue: stage sites 0..DIST-1 (50 x 16B per site)
    #pragma unroll
    for (int s = 0; s < DIST; s++) {
        const char* g = gsrc + (long)s * gstep;
        uint32_t dst = sbase + s * 800;
        cp16(dst + lane * 16, g + lane * 16);
        if (lane < 18) cp16(dst + (32 + lane) * 16, g + (32 + lane) * 16);
        cp_commit();
    }

    // init state (both halves compute the identical full v)
    ull vp[5];
    if (fwd) {
        const float2 f0 = g_feat[b];
        const ull* cfc = (const ull*)core_first;
        const ull* cfs = (const ull*)(core_first + 10);
        const ull c02 = pack2(f0.x, f0.x);
        const ull s02 = pack2(f0.y, f0.y);
        #pragma unroll
        for (int j = 0; j < 5; j++)
            vp[j] = fma2(s02, __ldg(cfs + j), mul2(c02, __ldg(cfc + j)));
    } else {
        const float2 fL = g_feat[(size_t)(NQ - 1) * BQ + b];
        const float2* cl = (const float2*)core_last;
        #pragma unroll
        for (int j = 0; j < 5; j++) {
            float2 qa = __ldg(cl + 2 * j);
            float2 qb = __ldg(cl + 2 * j + 1);
            vp[j] = pack2(fL.x * qa.x + fL.y * qa.y,
                          fL.x * qb.x + fL.y * qb.y);
        }
    }

    float2 fcur = *fp;

    for (int k = 0; k < NSTEP; k++) {
        cp_wait<DIST - 1>();          // site k staged
        __syncwarp();

        const float2 fnext = fp[(long)(k + 1) * fstep];

        const ulonglong2* hp = (const ulonglong2*)
            (&smem[wid][k & (RING - 1)][0] + half * 400);

        // dup-packed state
        const float2 q0 = unpack2(vp[0]);
        const float2 q1 = unpack2(vp[1]);
        const float2 q2 = unpack2(vp[2]);
        const float2 q3 = unpack2(vp[3]);
        const float2 q4 = unpack2(vp[4]);
        ull v2_[10];
        v2_[0] = pack2(q0.x, q0.x); v2_[1] = pack2(q0.y, q0.y);
        v2_[2] = pack2(q1.x, q1.x); v2_[3] = pack2(q1.y, q1.y);
        v2_[4] = pack2(q2.x, q2.x); v2_[5] = pack2(q2.y, q2.y);
        v2_[6] = pack2(q3.x, q3.x); v2_[7] = pack2(q3.y, q3.y);
        v2_[8] = pack2(q4.x, q4.x); v2_[9] = pack2(q4.y, q4.y);

        // own-half matvec: 5 output pairs, 10 fma2 each
        ull own[5];
        #pragma unroll
        for (int j = 0; j < 5; j++) {
            const ulonglong2 c0 = hp[j * 5 + 0];
            const ulonglong2 c1 = hp[j * 5 + 1];
            const ulonglong2 c2 = hp[j * 5 + 2];
            const ulonglong2 c3 = hp[j * 5 + 3];
            const ulonglong2 c4 = hp[j * 5 + 4];
            ull o = mul2(v2_[0], c0.x);
            o = fma2(v2_[1], c0.y, o);
            o = fma2(v2_[2], c1.x, o);
            o = fma2(v2_[3], c1.y, o);
            o = fma2(v2_[4], c2.x, o);
            o = fma2(v2_[5], c2.y, o);
            o = fma2(v2_[6], c3.x, o);
            o = fma2(v2_[7], c3.y, o);
            o = fma2(v2_[8], c4.x, o);
            o = fma2(v2_[9], c4.y, o);
            own[j] = o;
        }

        // scale by own coefficient, exchange with partner, combine
        const float myc = half ? fcur.y : fcur.x;
        const ull mc2 = pack2(myc, myc);
        #pragma unroll
        for (int j = 0; j < 5; j++) own[j] = mul2(mc2, own[j]);
        #pragma unroll
        for (int j = 0; j < 5; j++) {
            const ull oth = __shfl_xor_sync(0xffffffffu, own[j], 16);
            vp[j] = add2(own[j], oth);
        }
        fcur = fnext;

        // stage site k+DIST
        if (k + DIST < NSTEP) {
            const char* g = gsrc + (long)(k + DIST) * gstep;
            uint32_t dst = sbase + ((k + DIST) & (RING - 1)) * 800;
            cp16(dst + lane * 16, g + lane * 16);
            if (lane < 18) cp16(dst + (32 + lane) * 16, g + (32 + lane) * 16);
        }
        cp_commit();
    }

    if (half == 0) {
        if (fwd) {
            #pragma unroll
            for (int j = 0; j < 5; j++) g_V[(size_t)b * 5 + j] = vp[j];
        } else {
            #pragma unroll
            for (int j = 0; j < 5; j++) g_U[(size_t)b * 5 + j] = vp[j];
        }
    }
}

// ---------------------------------------------------------------------------
// K3: s[b] = dot(v,u);  logits[b,c] = s[b] * w[c],  w[c] = sum_d OT[c,d,0]
// ---------------------------------------------------------------------------
__global__ void combine_kernel(const float* __restrict__ ot,
                               float* __restrict__ out) {
    __shared__ float ws[10];
    const int tid = threadIdx.x;
    if (tid < 10) {
        float w = 0.f;
        #pragma unroll
        for (int d = 0; d < 10; d++) w += ot[tid * 10 + d];
        ws[tid] = w;
    }
    __syncthreads();

    const int b = blockIdx.x * blockDim.x + tid;
    if (b >= BQ) return;
    float s = 0.f;
    #pragma unroll
    for (int j = 0; j < 5; j++) {
        float2 a = unpack2(g_V[(size_t)b * 5 + j]);
        float2 u = unpack2(g_U[(size_t)b * 5 + j]);
        s += a.x * u.x + a.y * u.y;
    }
    #pragma unroll
    for (int c = 0; c < 10; c++)
        out[(size_t)b * 10 + c] = s * ws[c];
}

// ---------------------------------------------------------------------------
extern "C" void kernel_launch(void* const* d_in, const int* in_sizes, int n_in,
                              void* d_out, int out_size) {
    const float* x          = (const float*)d_in[0];  // (8192, 784)
    const float* core_first = (const float*)d_in[1];  // (1, 2, 10)
    const float* cores_mid  = (const float*)d_in[2];  // (782, 10, 2, 10)
    const float* core_last  = (const float*)d_in[3];  // (10, 2, 1)
    const float* out_t      = (const float*)d_in[4];  // (10, 10, 1)
    float* out = (float*)d_out;                       // (8192, 10)

    dim3 fgrid((NQ + 31) / 32, BQ / 32);
    dim3 fblk(32, 8);
    feat_kernel<<<fgrid, fblk>>>(x);
    prep_kernel<<<NSITES, 200>>>(cores_mid);

    chain_kernel<<<128, 256>>>(core_first, core_last);

    combine_kernel<<<BQ / 256, 256>>>(out_t, out);
}

// round 12
// speedup vs baseline: 1.3694x; 1.3051x over previous
#include <cuda_runtime.h>
#include <cuda_bf16.h>
#include <cstddef>
#include <cstdint>

#define BQ 8192
#define NQ 784
#define NSITES 782
#define NSTEP 391          // steps per half-chain (sites 0..390 of the stream)
#define NPAIR 195          // paired iterations (sites 0..389), +1 remainder
#define RING 8             // smem stages (sites) per warp

typedef unsigned long long ull;

// Scratch
__device__ float2     g_feat[(size_t)NQ * BQ];         // [site][batch] (cos,sin)
__device__ ulonglong2 g_coresT[(size_t)NSITES * 50];   // transposed cores (backward)
__device__ ull        g_V[(size_t)BQ * 5];
__device__ ull        g_U[(size_t)BQ * 5];

// ---------------- packed f32x2 helpers ----------------
__device__ __forceinline__ ull pack2(float lo, float hi) {
    ull r;
    asm("mov.b64 %0, {%1, %2};" : "=l"(r)
        : "r"(__float_as_uint(lo)), "r"(__float_as_uint(hi)));
    return r;
}
__device__ __forceinline__ float2 unpack2(ull v) {
    unsigned int lo, hi;
    asm("mov.b64 {%0, %1}, %2;" : "=r"(lo), "=r"(hi) : "l"(v));
    return make_float2(__uint_as_float(lo), __uint_as_float(hi));
}
__device__ __forceinline__ ull fma2(ull a, ull b, ull c) {
    ull d;
    asm("fma.rn.f32x2 %0, %1, %2, %3;" : "=l"(d) : "l"(a), "l"(b), "l"(c));
    return d;
}
__device__ __forceinline__ ull mul2(ull a, ull b) {
    ull d;
    asm("mul.rn.f32x2 %0, %1, %2;" : "=l"(d) : "l"(a), "l"(b));
    return d;
}

// ---------------- cp.async helpers ----------------
__device__ __forceinline__ void cp16(uint32_t saddr, const void* gptr) {
    asm volatile("cp.async.cg.shared.global [%0], [%1], 16;"
                 :: "r"(saddr), "l"(gptr) : "memory");
}
__device__ __forceinline__ void cp_commit() {
    asm volatile("cp.async.commit_group;" ::: "memory");
}
template <int N> __device__ __forceinline__ void cp_wait() {
    asm volatile("cp.async.wait_group %0;" :: "n"(N) : "memory");
}

// stage one 800B site matrix into smem (warp-collective, 50 x 16B)
__device__ __forceinline__ void stage_site(uint32_t dst, const char* g, int lane) {
    cp16(dst + lane * 16, g + lane * 16);
    if (lane < 18) cp16(dst + (32 + lane) * 16, g + (32 + lane) * 16);
}

// ---------------------------------------------------------------------------
// K1: featurize + transpose. x:(B,N) -> g_feat:(N,B) float2 (cos, sin)
// ---------------------------------------------------------------------------
__global__ void feat_kernel(const float* __restrict__ x) {
    __shared__ float2 tf[32][33];
    const int tx = threadIdx.x;
    const int ty = threadIdx.y;
    const int n0 = blockIdx.x * 32;
    const int b0 = blockIdx.y * 32;

    #pragma unroll
    for (int j = 0; j < 32; j += 8) {
        int n = n0 + tx;
        int b = b0 + ty + j;
        if (n < NQ) {
            float val = x[(size_t)b * NQ + n];
            float s, c;
            sincospif(val, &s, &c);
            tf[tx][ty + j] = make_float2(c, s);
        }
    }
    __syncthreads();
    #pragma unroll
    for (int j = 0; j < 32; j += 8) {
        int n = n0 + ty + j;
        int b = b0 + tx;
        if (n < NQ) g_feat[(size_t)n * BQ + b] = tf[ty + j][tx];
    }
}

// ---------------------------------------------------------------------------
// K1b: transpose cores for the backward half: src[i][l][d][r] -> dst[i][r][d][l]
// ---------------------------------------------------------------------------
__global__ void transpose_cores(const float* __restrict__ src) {
    const int site = blockIdx.x;
    const int o = threadIdx.x;          // 0..199 : o = r*20 + d*10 + l
    const int r = o / 20;
    const int d = (o % 20) / 10;
    const int l = o % 10;
    ((float*)g_coresT)[(size_t)site * 200 + o] =
        src[(size_t)site * 200 + l * 20 + d * 10 + r];
}

// ---------------------------------------------------------------------------
// one recurrence step: vp = fc * (A^T v) + fs * (B^T v), from smem row.
// ---------------------------------------------------------------------------
__device__ __forceinline__ void chain_step(const ulonglong2* __restrict__ row,
                                           float2 f, ull vp[5]) {
    float2 vf0 = unpack2(vp[0]);
    float2 vf1 = unpack2(vp[1]);
    float2 vf2 = unpack2(vp[2]);
    float2 vf3 = unpack2(vp[3]);
    float2 vf4 = unpack2(vp[4]);

    ull a0, a1, a2, a3, a4, c0, c1, c2, c3, c4;

    #pragma unroll
    for (int l = 0; l < 10; l++) {
        const ulonglong2 p0 = row[l * 5 + 0];
        const ulonglong2 p1 = row[l * 5 + 1];
        const ulonglong2 p2 = row[l * 5 + 2];
        const ulonglong2 p3 = row[l * 5 + 3];
        const ulonglong2 p4 = row[l * 5 + 4];
        float vl;
        switch (l) {
            case 0: vl = vf0.x; break; case 1: vl = vf0.y; break;
            case 2: vl = vf1.x; break; case 3: vl = vf1.y; break;
            case 4: vl = vf2.x; break; case 5: vl = vf2.y; break;
            case 6: vl = vf3.x; break; case 7: vl = vf3.y; break;
            case 8: vl = vf4.x; break; default: vl = vf4.y; break;
        }
        const ull vl2 = pack2(vl, vl);
        if (l == 0) {
            a0 = mul2(vl2, p0.x); a1 = mul2(vl2, p0.y);
            a2 = mul2(vl2, p1.x); a3 = mul2(vl2, p1.y);
            a4 = mul2(vl2, p2.x);
            c0 = mul2(vl2, p2.y);
            c1 = mul2(vl2, p3.x); c2 = mul2(vl2, p3.y);
            c3 = mul2(vl2, p4.x); c4 = mul2(vl2, p4.y);
        } else {
            a0 = fma2(vl2, p0.x, a0); a1 = fma2(vl2, p0.y, a1);
            a2 = fma2(vl2, p1.x, a2); a3 = fma2(vl2, p1.y, a3);
            a4 = fma2(vl2, p2.x, a4);
            c0 = fma2(vl2, p2.y, c0);
            c1 = fma2(vl2, p3.x, c1); c2 = fma2(vl2, p3.y, c2);
            c3 = fma2(vl2, p4.x, c3); c4 = fma2(vl2, p4.y, c4);
        }
    }
    const ull fc2 = pack2(f.x, f.x);
    const ull fs2 = pack2(f.y, f.y);
    vp[0] = fma2(fs2, c0, mul2(fc2, a0));
    vp[1] = fma2(fs2, c1, mul2(fc2, a1));
    vp[2] = fma2(fs2, c2, mul2(fc2, a2));
    vp[3] = fma2(fs2, c3, mul2(fc2, a3));
    vp[4] = fma2(fs2, c4, mul2(fc2, a4));
}

// ---------------------------------------------------------------------------
// K2: per-thread full-r chain, paired iterations (one wait/sync per 2 sites),
// RING=8 smem ring, stage-ahead 3 pairs, pure pointer bumps.
// grid=128, block=128. Blocks [0,64): forward; [64,128): backward.
// ---------------------------------------------------------------------------
__global__ __launch_bounds__(128, 1)
void chain_kernel(const float* __restrict__ core_first,
                  const float* __restrict__ cores_mid,
                  const float* __restrict__ core_last) {
    __shared__ __align__(16) char smem[4][RING][800];

    const int tid  = threadIdx.x;
    const int wid  = tid >> 5;
    const int lane = tid & 31;
    const bool fwd = (blockIdx.x < 64);
    const int b = (fwd ? blockIdx.x : blockIdx.x - 64) * 128 + tid;

    const char* gsrc;
    long gstep;
    const float2* fp;
    long fstep;
    if (fwd) {
        gsrc  = (const char*)cores_mid;                      // site 0 ascending
        gstep = 800;
        fp    = g_feat + (size_t)BQ + b;                     // feature of step 0
        fstep = BQ;
    } else {
        gsrc  = (const char*)(g_coresT + (size_t)(NSITES - 1) * 50); // site 781 desc
        gstep = -800;
        fp    = g_feat + (size_t)(NQ - 2) * BQ + b;
        fstep = -(long)BQ;
    }

    const uint32_t sbase = (uint32_t)__cvta_generic_to_shared(&smem[wid][0][0]);

    // prologue: stage pairs 0,1,2 (sites 0..5), one commit group per pair
    {
        const char* g = gsrc;
        #pragma unroll
        for (int p = 0; p < 3; p++) {
            stage_site(sbase + (2 * p) * 800, g, lane);          g += gstep;
            stage_site(sbase + (2 * p + 1) * 800, g, lane);      g += gstep;
            cp_commit();
        }
    }
    const char* gstage = gsrc + 6 * gstep;     // next site to stage (site 6)

    // init state
    ull vp[5];
    if (fwd) {
        const float2 f0 = g_feat[b];
        const ull* cfc = (const ull*)core_first;
        const ull* cfs = (const ull*)(core_first + 10);
        const ull c02 = pack2(f0.x, f0.x);
        const ull s02 = pack2(f0.y, f0.y);
        #pragma unroll
        for (int j = 0; j < 5; j++)
            vp[j] = fma2(s02, __ldg(cfs + j), mul2(c02, __ldg(cfc + j)));
    } else {
        const float2 fL = g_feat[(size_t)(NQ - 1) * BQ + b];
        const float2* cl = (const float2*)core_last;
        #pragma unroll
        for (int j = 0; j < 5; j++) {
            float2 qa = __ldg(cl + 2 * j);
            float2 qb = __ldg(cl + 2 * j + 1);
            vp[j] = pack2(fL.x * qa.x + fL.y * qa.y,
                          fL.x * qb.x + fL.y * qb.y);
        }
    }

    // feature registers: fc0/fc1 = current pair; prefetch pointer for next pair
    float2 fc0 = fp[0];
    float2 fc1 = fp[fstep];
    const float2* fpre = fp + 2 * fstep;

    int slot = 0;   // smem slot of current pair's first site (0,2,4,6,0,..)

    for (int p = 0; p < NPAIR; p++) {
        cp_wait<2>();               // current pair staged
        __syncwarp();

        // prefetch next pair's features
        const float2 fn0 = fpre[0];
        const float2 fn1 = fpre[fstep];
        fpre += 2 * fstep;

        const char* base = &smem[wid][slot][0];
        chain_step((const ulonglong2*)base, fc0, vp);
        chain_step((const ulonglong2*)(base + 800), fc1, vp);
        fc0 = fn0;
        fc1 = fn1;

        // stage pair p+3 (sites 2p+6, 2p+7) — unconditional, always in-bounds
        const int wslot = (slot + 6) & 7;
        stage_site(sbase + wslot * 800, gstage, lane);           gstage += gstep;
        stage_site(sbase + (wslot + 1) * 800, gstage, lane);     gstage += gstep;
        cp_commit();

        slot = (slot + 2) & 7;
    }

    // remainder: step 390 (pair 195, first site)
    cp_wait<2>();
    __syncwarp();
    chain_step((const ulonglong2*)&smem[wid][slot][0], fc0, vp);

    if (fwd) {
        #pragma unroll
        for (int j = 0; j < 5; j++) g_V[(size_t)b * 5 + j] = vp[j];
    } else {
        #pragma unroll
        for (int j = 0; j < 5; j++) g_U[(size_t)b * 5 + j] = vp[j];
    }
}

// ---------------------------------------------------------------------------
// K3: s[b] = dot(v,u);  logits[b,c] = s[b] * w[c],  w[c] = sum_d OT[c,d,0]
// ---------------------------------------------------------------------------
__global__ void combine_kernel(const float* __restrict__ ot,
                               float* __restrict__ out) {
    __shared__ float ws[10];
    const int tid = threadIdx.x;
    if (tid < 10) {
        float w = 0.f;
        #pragma unroll
        for (int d = 0; d < 10; d++) w += ot[tid * 10 + d];
        ws[tid] = w;
    }
    __syncthreads();

    const int b = blockIdx.x * blockDim.x + tid;
    if (b >= BQ) return;
    float s = 0.f;
    #pragma unroll
    for (int j = 0; j < 5; j++) {
        float2 a = unpack2(g_V[(size_t)b * 5 + j]);
        float2 u = unpack2(g_U[(size_t)b * 5 + j]);
        s += a.x * u.x + a.y * u.y;
    }
    #pragma unroll
    for (int c = 0; c < 10; c++)
        out[(size_t)b * 10 + c] = s * ws[c];
}

// ---------------------------------------------------------------------------
extern "C" void kernel_launch(void* const* d_in, const int* in_sizes, int n_in,
                              void* d_out, int out_size) {
    const float* x          = (const float*)d_in[0];  // (8192, 784)
    const float* core_first = (const float*)d_in[1];  // (1, 2, 10)
    const float* cores_mid  = (const float*)d_in[2];  // (782, 10, 2, 10)
    const float* core_last  = (const float*)d_in[3];  // (10, 2, 1)
    const float* out_t      = (const float*)d_in[4];  // (10, 10, 1)
    float* out = (float*)d_out;                       // (8192, 10)

    dim3 fgrid((NQ + 31) / 32, BQ / 32);
    dim3 fblk(32, 8);
    feat_kernel<<<fgrid, fblk>>>(x);
    transpose_cores<<<NSITES, 200>>>(cores_mid);

    chain_kernel<<<128, 128>>>(core_first, cores_mid, core_last);

    combine_kernel<<<BQ / 256, 256>>>(out_t, out);
}

// round 15
// speedup vs baseline: 1.6477x; 1.2033x over previous
#include <cuda_runtime.h>
#include <cuda_bf16.h>
#include <cstddef>
#include <cstdint>

#define BQ 8192
#define NQ 784
#define NSITES 782
#define NSTEP 391          // steps per half-chain
#define NQUAD 97           // quad iterations (sites 0..387), +3 remainder
#define RING 12            // smem stages (sites) per warp

typedef unsigned long long ull;

// Scratch
__device__ float2     g_feat[(size_t)NQ * BQ];         // [site][batch] (cos,sin)
__device__ ulonglong2 g_coresT[(size_t)NSITES * 50];   // transposed cores (backward)
__device__ ull        g_V[(size_t)BQ * 5];
__device__ ull        g_U[(size_t)BQ * 5];

// ---------------- packed f32x2 helpers ----------------
__device__ __forceinline__ ull pack2(float lo, float hi) {
    ull r;
    asm("mov.b64 %0, {%1, %2};" : "=l"(r)
        : "r"(__float_as_uint(lo)), "r"(__float_as_uint(hi)));
    return r;
}
__device__ __forceinline__ float2 unpack2(ull v) {
    unsigned int lo, hi;
    asm("mov.b64 {%0, %1}, %2;" : "=r"(lo), "=r"(hi) : "l"(v));
    return make_float2(__uint_as_float(lo), __uint_as_float(hi));
}
__device__ __forceinline__ ull fma2(ull a, ull b, ull c) {
    ull d;
    asm("fma.rn.f32x2 %0, %1, %2, %3;" : "=l"(d) : "l"(a), "l"(b), "l"(c));
    return d;
}
__device__ __forceinline__ ull mul2(ull a, ull b) {
    ull d;
    asm("mul.rn.f32x2 %0, %1, %2;" : "=l"(d) : "l"(a), "l"(b));
    return d;
}

// ---------------- cp.async helpers ----------------
__device__ __forceinline__ void cp16(uint32_t saddr, const void* gptr) {
    asm volatile("cp.async.cg.shared.global [%0], [%1], 16;"
                 :: "r"(saddr), "l"(gptr) : "memory");
}
__device__ __forceinline__ void cp_commit() {
    asm volatile("cp.async.commit_group;" ::: "memory");
}
template <int N> __device__ __forceinline__ void cp_wait() {
    asm volatile("cp.async.wait_group %0;" :: "n"(N) : "memory");
}

// stage one 800B site matrix into smem (warp-collective, 50 x 16B)
__device__ __forceinline__ void stage_site(uint32_t dst, const char* g, int lane) {
    cp16(dst + lane * 16, g + lane * 16);
    if (lane < 18) cp16(dst + (32 + lane) * 16, g + (32 + lane) * 16);
}

// ---------------------------------------------------------------------------
// K1: featurize + transpose. x:(B,N) -> g_feat:(N,B) float2 (cos, sin)
// ---------------------------------------------------------------------------
__global__ void feat_kernel(const float* __restrict__ x) {
    __shared__ float2 tf[32][33];
    const int tx = threadIdx.x;
    const int ty = threadIdx.y;
    const int n0 = blockIdx.x * 32;
    const int b0 = blockIdx.y * 32;

    #pragma unroll
    for (int j = 0; j < 32; j += 8) {
        int n = n0 + tx;
        int b = b0 + ty + j;
        if (n < NQ) {
            float val = x[(size_t)b * NQ + n];
            float s, c;
            sincospif(val, &s, &c);
            tf[tx][ty + j] = make_float2(c, s);
        }
    }
    __syncthreads();
    #pragma unroll
    for (int j = 0; j < 32; j += 8) {
        int n = n0 + ty + j;
        int b = b0 + tx;
        if (n < NQ) g_feat[(size_t)n * BQ + b] = tf[ty + j][tx];
    }
}

// ---------------------------------------------------------------------------
// K1b: transpose cores for the backward half: src[i][l][d][r] -> dst[i][r][d][l]
// ---------------------------------------------------------------------------
__global__ void transpose_cores(const float* __restrict__ src) {
    const int site = blockIdx.x;
    const int o = threadIdx.x;          // 0..199 : o = r*20 + d*10 + l
    const int r = o / 20;
    const int d = (o % 20) / 10;
    const int l = o % 10;
    ((float*)g_coresT)[(size_t)site * 200 + o] =
        src[(size_t)site * 200 + l * 20 + d * 10 + r];
}

// ---------------------------------------------------------------------------
// one recurrence step: vp = fc * (A^T v) + fs * (B^T v), from smem row.
// ---------------------------------------------------------------------------
__device__ __forceinline__ void chain_step(const ulonglong2* __restrict__ row,
                                           float2 f, ull vp[5]) {
    float2 vf0 = unpack2(vp[0]);
    float2 vf1 = unpack2(vp[1]);
    float2 vf2 = unpack2(vp[2]);
    float2 vf3 = unpack2(vp[3]);
    float2 vf4 = unpack2(vp[4]);

    ull a0, a1, a2, a3, a4, c0, c1, c2, c3, c4;

    #pragma unroll
    for (int l = 0; l < 10; l++) {
        const ulonglong2 p0 = row[l * 5 + 0];
        const ulonglong2 p1 = row[l * 5 + 1];
        const ulonglong2 p2 = row[l * 5 + 2];
        const ulonglong2 p3 = row[l * 5 + 3];
        const ulonglong2 p4 = row[l * 5 + 4];
        float vl;
        switch (l) {
            case 0: vl = vf0.x; break; case 1: vl = vf0.y; break;
            case 2: vl = vf1.x; break; case 3: vl = vf1.y; break;
            case 4: vl = vf2.x; break; case 5: vl = vf2.y; break;
            case 6: vl = vf3.x; break; case 7: vl = vf3.y; break;
            case 8: vl = vf4.x; break; default: vl = vf4.y; break;
        }
        const ull vl2 = pack2(vl, vl);
        if (l == 0) {
            a0 = mul2(vl2, p0.x); a1 = mul2(vl2, p0.y);
            a2 = mul2(vl2, p1.x); a3 = mul2(vl2, p1.y);
            a4 = mul2(vl2, p2.x);
            c0 = mul2(vl2, p2.y);
            c1 = mul2(vl2, p3.x); c2 = mul2(vl2, p3.y);
            c3 = mul2(vl2, p4.x); c4 = mul2(vl2, p4.y);
        } else {
            a0 = fma2(vl2, p0.x, a0); a1 = fma2(vl2, p0.y, a1);
            a2 = fma2(vl2, p1.x, a2); a3 = fma2(vl2, p1.y, a3);
            a4 = fma2(vl2, p2.x, a4);
            c0 = fma2(vl2, p2.y, c0);
            c1 = fma2(vl2, p3.x, c1); c2 = fma2(vl2, p3.y, c2);
            c3 = fma2(vl2, p4.x, c3); c4 = fma2(vl2, p4.y, c4);
        }
    }
    const ull fc2 = pack2(f.x, f.x);
    const ull fs2 = pack2(f.y, f.y);
    vp[0] = fma2(fs2, c0, mul2(fc2, a0));
    vp[1] = fma2(fs2, c1, mul2(fc2, a1));
    vp[2] = fma2(fs2, c2, mul2(fc2, a2));
    vp[3] = fma2(fs2, c3, mul2(fc2, a3));
    vp[4] = fma2(fs2, c4, mul2(fc2, a4));
}

// ---------------------------------------------------------------------------
// K2: per-thread full-r chain, QUAD iterations (one wait/sync per 4 sites),
// RING=12 smem ring, stage-ahead 2 quads, pure pointer bumps.
// grid=128, block=128. Blocks [0,64): forward; [64,128): backward.
// ---------------------------------------------------------------------------
__global__ __launch_bounds__(128, 1)
void chain_kernel(const float* __restrict__ core_first,
                  const float* __restrict__ cores_mid,
                  const float* __restrict__ core_last) {
    __shared__ __align__(16) char smem[4][RING][800];   // 38.4 KB

    const int tid  = threadIdx.x;
    const int wid  = tid >> 5;
    const int lane = tid & 31;
    const bool fwd = (blockIdx.x < 64);
    const int b = (fwd ? blockIdx.x : blockIdx.x - 64) * 128 + tid;

    const char* gsrc;
    long gstep;
    const float2* fp;
    long fstep;
    if (fwd) {
        gsrc  = (const char*)cores_mid;                      // site 0 ascending
        gstep = 800;
        fp    = g_feat + (size_t)BQ + b;                     // feature of step 0
        fstep = BQ;
    } else {
        gsrc  = (const char*)(g_coresT + (size_t)(NSITES - 1) * 50); // site 781 desc
        gstep = -800;
        fp    = g_feat + (size_t)(NQ - 2) * BQ + b;
        fstep = -(long)BQ;
    }

    const uint32_t sbase = (uint32_t)__cvta_generic_to_shared(&smem[wid][0][0]);

    // prologue: stage quads 0,1 (sites 0..7), one commit group per quad
    {
        const char* g = gsrc;
        #pragma unroll
        for (int q = 0; q < 2; q++) {
            #pragma unroll
            for (int s = 0; s < 4; s++) {
                stage_site(sbase + (4 * q + s) * 800, g, lane);
                g += gstep;
            }
            cp_commit();
        }
    }
    const char* gstage = gsrc + 8 * gstep;     // next site to stage (site 8)

    // init state
    ull vp[5];
    if (fwd) {
        const float2 f0 = g_feat[b];
        const ull* cfc = (const ull*)core_first;
        const ull* cfs = (const ull*)(core_first + 10);
        const ull c02 = pack2(f0.x, f0.x);
        const ull s02 = pack2(f0.y, f0.y);
        #pragma unroll
        for (int j = 0; j < 5; j++)
            vp[j] = fma2(s02, __ldg(cfs + j), mul2(c02, __ldg(cfc + j)));
    } else {
        const float2 fL = g_feat[(size_t)(NQ - 1) * BQ + b];
        const float2* cl = (const float2*)core_last;
        #pragma unroll
        for (int j = 0; j < 5; j++) {
            float2 qa = __ldg(cl + 2 * j);
            float2 qb = __ldg(cl + 2 * j + 1);
            vp[j] = pack2(fL.x * qa.x + fL.y * qa.y,
                          fL.x * qb.x + fL.y * qb.y);
        }
    }

    // feature regs for current quad; prefetch pointer for next quad
    float2 fc0 = fp[0];
    float2 fc1 = fp[fstep];
    float2 fc2 = fp[2 * fstep];
    float2 fc3 = fp[3 * fstep];
    const float2* fpre = fp + 4 * fstep;

    int slot = 0;   // smem slot (site units) of current quad: 0,4,8,0,...

    for (int q = 0; q < NQUAD; q++) {
        cp_wait<1>();               // current quad staged
        __syncwarp();

        // prefetch next quad's features
        const float2 fn0 = fpre[0];
        const float2 fn1 = fpre[fstep];
        const float2 fn2 = fpre[2 * fstep];
        const float2 fn3 = fpre[3 * fstep];
        fpre += 4 * fstep;

        const char* base = &smem[wid][slot][0];
        chain_step((const ulonglong2*)base, fc0, vp);
        chain_step((const ulonglong2*)(base + 800), fc1, vp);
        chain_step((const ulonglong2*)(base + 1600), fc2, vp);
        chain_step((const ulonglong2*)(base + 2400), fc3, vp);
        fc0 = fn0; fc1 = fn1; fc2 = fn2; fc3 = fn3;

        // stage quad q+2 (sites 4q+8..11) — unconditional, always in-bounds
        int wslot = slot + 8; if (wslot >= RING) wslot -= RING;
        uint32_t dst = sbase + wslot * 800;
        #pragma unroll
        for (int s = 0; s < 4; s++) {
            stage_site(dst + s * 800, gstage, lane);
            gstage += gstep;
        }
        cp_commit();

        slot += 4; if (slot >= RING) slot -= RING;
    }

    // remainder: sites 388,389,390 (quad 97, staged at 'slot')
    cp_wait<0>();
    __syncwarp();
    {
        const char* base = &smem[wid][slot][0];
        chain_step((const ulonglong2*)base, fc0, vp);
        chain_step((const ulonglong2*)(base + 800), fc1, vp);
        chain_step((const ulonglong2*)(base + 1600), fc2, vp);
    }

    if (fwd) {
        #pragma unroll
        for (int j = 0; j < 5; j++) g_V[(size_t)b * 5 + j] = vp[j];
    } else {
        #pragma unroll
        for (int j = 0; j < 5; j++) g_U[(size_t)b * 5 + j] = vp[j];
    }
}

// ---------------------------------------------------------------------------
// K3: s[b] = dot(v,u);  logits[b,c] = s[b] * w[c],  w[c] = sum_d OT[c,d,0]
// ---------------------------------------------------------------------------
__global__ void combine_kernel(const float* __restrict__ ot,
                               float* __restrict__ out) {
    __shared__ float ws[10];
    const int tid = threadIdx.x;
    if (tid < 10) {
        float w = 0.f;
        #pragma unroll
        for (int d = 0; d < 10; d++) w += ot[tid * 10 + d];
        ws[tid] = w;
    }
    __syncthreads();

    const int b = blockIdx.x * blockDim.x + tid;
    if (b >= BQ) return;
    float s = 0.f;
    #pragma unroll
    for (int j = 0; j < 5; j++) {
        float2 a = unpack2(g_V[(size_t)b * 5 + j]);
        float2 u = unpack2(g_U[(size_t)b * 5 + j]);
        s += a.x * u.x + a.y * u.y;
    }
    #pragma unroll
    for (int c = 0; c < 10; c++)
        out[(size_t)b * 10 + c] = s * ws[c];
}

// ---------------------------------------------------------------------------
extern "C" void kernel_launch(void* const* d_in, const int* in_sizes, int n_in,
                              void* d_out, int out_size) {
    const float* x          = (const float*)d_in[0];  // (8192, 784)
    const float* core_first = (const float*)d_in[1];  // (1, 2, 10)
    const float* cores_mid  = (const float*)d_in[2];  // (782, 10, 2, 10)
    const float* core_last  = (const float*)d_in[3];  // (10, 2, 1)
    const float* out_t      = (const float*)d_in[4];  // (10, 10, 1)
    float* out = (float*)d_out;                       // (8192, 10)

    dim3 fgrid((NQ + 31) / 32, BQ / 32);
    dim3 fblk(32, 8);
    feat_kernel<<<fgrid, fblk>>>(x);
    transpose_cores<<<NSITES, 200>>>(cores_mid);

    chain_kernel<<<128, 128>>>(core_first, cores_mid, core_last);

    combine_kernel<<<BQ / 128, 128>>>(out_t, out);
}

// round 17
// speedup vs baseline: 1.6738x; 1.0158x over previous
#include <cuda_runtime.h>
#include <cuda_bf16.h>
#include <cstddef>
#include <cstdint>

#define BQ 8192
#define NQ 784
#define NSITES 782
#define NSTEP 391          // steps per half-chain
#define NQUAD 97           // quad iterations (sites 0..387), +3 remainder
#define RING 12            // smem stages (sites) per warp

typedef unsigned long long ull;

// Scratch
__device__ float2     g_feat[(size_t)NQ * BQ];         // [site][batch] (cos,sin)
__device__ ulonglong2 g_coresT[(size_t)NSITES * 50];   // transposed cores (backward)
__device__ ull        g_V[(size_t)5 * BQ];             // [j][b] coalesced
__device__ ull        g_U[(size_t)5 * BQ];             // [j][b] coalesced

// ---------------- packed f32x2 helpers ----------------
__device__ __forceinline__ ull pack2(float lo, float hi) {
    ull r;
    asm("mov.b64 %0, {%1, %2};" : "=l"(r)
        : "r"(__float_as_uint(lo)), "r"(__float_as_uint(hi)));
    return r;
}
__device__ __forceinline__ float2 unpack2(ull v) {
    unsigned int lo, hi;
    asm("mov.b64 {%0, %1}, %2;" : "=r"(lo), "=r"(hi) : "l"(v));
    return make_float2(__uint_as_float(lo), __uint_as_float(hi));
}
__device__ __forceinline__ ull fma2(ull a, ull b, ull c) {
    ull d;
    asm("fma.rn.f32x2 %0, %1, %2, %3;" : "=l"(d) : "l"(a), "l"(b), "l"(c));
    return d;
}
__device__ __forceinline__ ull mul2(ull a, ull b) {
    ull d;
    asm("mul.rn.f32x2 %0, %1, %2;" : "=l"(d) : "l"(a), "l"(b));
    return d;
}

// ---------------- cp.async helpers ----------------
__device__ __forceinline__ void cp16(uint32_t saddr, const void* gptr) {
    asm volatile("cp.async.cg.shared.global [%0], [%1], 16;"
                 :: "r"(saddr), "l"(gptr) : "memory");
}
__device__ __forceinline__ void cp_commit() {
    asm volatile("cp.async.commit_group;" ::: "memory");
}
template <int N> __device__ __forceinline__ void cp_wait() {
    asm volatile("cp.async.wait_group %0;" :: "n"(N) : "memory");
}

// stage one 800B site matrix into smem (warp-collective, 50 x 16B)
__device__ __forceinline__ void stage_site(uint32_t dst, const char* g, int lane) {
    cp16(dst + lane * 16, g + lane * 16);
    if (lane < 18) cp16(dst + (32 + lane) * 16, g + (32 + lane) * 16);
}

// ---------------------------------------------------------------------------
// fast sin/cos(pi*x) for x in [0,1):  y = x-1/2, z = y^2
//   sin(pi x) = cos(pi y)  : even Taylor, |err| ~ 6e-9
//   cos(pi x) = -sin(pi y) : odd Taylor,  |err| ~ 6e-8
// ---------------------------------------------------------------------------
__device__ __forceinline__ float2 sincos_pi01(float x) {
    const float y = x - 0.5f;
    const float z = y * y;
    // q = cos(pi y)
    float q = fmaf(z, 0.00192602f, -0.02580689f);
    q = fmaf(z, q, 0.23533063f);
    q = fmaf(z, q, -1.33526277f);
    q = fmaf(z, q, 4.05871213f);
    q = fmaf(z, q, -4.93480220f);
    q = fmaf(z, q, 1.0f);
    // p = sin(pi y)/y
    float p = fmaf(z, -0.00737043f, 0.08214589f);
    p = fmaf(z, p, -0.59926453f);
    p = fmaf(z, p, 2.55016404f);
    p = fmaf(z, p, -5.16771278f);
    p = fmaf(z, p, 3.14159265f);
    // cos(pi x) = -p*y ; sin(pi x) = q
    return make_float2(-p * y, q);
}

// ---------------------------------------------------------------------------
// K1: featurize + transpose. x:(B,N) -> g_feat:(N,B) float2 (cos, sin)
// ---------------------------------------------------------------------------
__global__ void feat_kernel(const float* __restrict__ x) {
    __shared__ float2 tf[32][33];
    const int tx = threadIdx.x;
    const int ty = threadIdx.y;
    const int n0 = blockIdx.x * 32;
    const int b0 = blockIdx.y * 32;

    #pragma unroll
    for (int j = 0; j < 32; j += 8) {
        int n = n0 + tx;
        int b = b0 + ty + j;
        if (n < NQ) {
            tf[tx][ty + j] = sincos_pi01(x[(size_t)b * NQ + n]);
        }
    }
    __syncthreads();
    #pragma unroll
    for (int j = 0; j < 32; j += 8) {
        int n = n0 + ty + j;
        int b = b0 + tx;
        if (n < NQ) g_feat[(size_t)n * BQ + b] = tf[ty + j][tx];
    }
}

// ---------------------------------------------------------------------------
// K1b: transpose cores for the backward half: src[i][l][d][r] -> dst[i][r][d][l]
// ---------------------------------------------------------------------------
__global__ void transpose_cores(const float* __restrict__ src) {
    const int site = blockIdx.x;
    const int o = threadIdx.x;          // 0..199 : o = r*20 + d*10 + l
    const int r = o / 20;
    const int d = (o % 20) / 10;
    const int l = o % 10;
    ((float*)g_coresT)[(size_t)site * 200 + o] =
        src[(size_t)site * 200 + l * 20 + d * 10 + r];
}

// ---------------------------------------------------------------------------
// one recurrence step: vp = fc * (A^T v) + fs * (B^T v), from smem row.
// ---------------------------------------------------------------------------
__device__ __forceinline__ void chain_step(const ulonglong2* __restrict__ row,
                                           float2 f, ull vp[5]) {
    float2 vf0 = unpack2(vp[0]);
    float2 vf1 = unpack2(vp[1]);
    float2 vf2 = unpack2(vp[2]);
    float2 vf3 = unpack2(vp[3]);
    float2 vf4 = unpack2(vp[4]);

    ull a0, a1, a2, a3, a4, c0, c1, c2, c3, c4;

    #pragma unroll
    for (int l = 0; l < 10; l++) {
        const ulonglong2 p0 = row[l * 5 + 0];
        const ulonglong2 p1 = row[l * 5 + 1];
        const ulonglong2 p2 = row[l * 5 + 2];
        const ulonglong2 p3 = row[l * 5 + 3];
        const ulonglong2 p4 = row[l * 5 + 4];
        float vl;
        switch (l) {
            case 0: vl = vf0.x; break; case 1: vl = vf0.y; break;
            case 2: vl = vf1.x; break; case 3: vl = vf1.y; break;
            case 4: vl = vf2.x; break; case 5: vl = vf2.y; break;
            case 6: vl = vf3.x; break; case 7: vl = vf3.y; break;
            case 8: vl = vf4.x; break; default: vl = vf4.y; break;
        }
        const ull vl2 = pack2(vl, vl);
        if (l == 0) {
            a0 = mul2(vl2, p0.x); a1 = mul2(vl2, p0.y);
            a2 = mul2(vl2, p1.x); a3 = mul2(vl2, p1.y);
            a4 = mul2(vl2, p2.x);
            c0 = mul2(vl2, p2.y);
            c1 = mul2(vl2, p3.x); c2 = mul2(vl2, p3.y);
            c3 = mul2(vl2, p4.x); c4 = mul2(vl2, p4.y);
        } else {
            a0 = fma2(vl2, p0.x, a0); a1 = fma2(vl2, p0.y, a1);
            a2 = fma2(vl2, p1.x, a2); a3 = fma2(vl2, p1.y, a3);
            a4 = fma2(vl2, p2.x, a4);
            c0 = fma2(vl2, p2.y, c0);
            c1 = fma2(vl2, p3.x, c1); c2 = fma2(vl2, p3.y, c2);
            c3 = fma2(vl2, p4.x, c3); c4 = fma2(vl2, p4.y, c4);
        }
    }
    const ull fc2 = pack2(f.x, f.x);
    const ull fs2 = pack2(f.y, f.y);
    vp[0] = fma2(fs2, c0, mul2(fc2, a0));
    vp[1] = fma2(fs2, c1, mul2(fc2, a1));
    vp[2] = fma2(fs2, c2, mul2(fc2, a2));
    vp[3] = fma2(fs2, c3, mul2(fc2, a3));
    vp[4] = fma2(fs2, c4, mul2(fc2, a4));
}

// ---------------------------------------------------------------------------
// K2: per-thread full-r chain, QUAD iterations (one wait/sync per 4 sites),
// RING=12 smem ring, stage-ahead 2 quads, pure pointer bumps.
// grid=128, block=128. Blocks [0,64): forward; [64,128): backward.
// ---------------------------------------------------------------------------
__global__ __launch_bounds__(128, 1)
void chain_kernel(const float* __restrict__ core_first,
                  const float* __restrict__ cores_mid,
                  const float* __restrict__ core_last) {
    __shared__ __align__(16) char smem[4][RING][800];   // 38.4 KB

    const int tid  = threadIdx.x;
    const int wid  = tid >> 5;
    const int lane = tid & 31;
    const bool fwd = (blockIdx.x < 64);
    const int b = (fwd ? blockIdx.x : blockIdx.x - 64) * 128 + tid;

    const char* gsrc;
    long gstep;
    const float2* fp;
    long fstep;
    if (fwd) {
        gsrc  = (const char*)cores_mid;                      // site 0 ascending
        gstep = 800;
        fp    = g_feat + (size_t)BQ + b;                     // feature of step 0
        fstep = BQ;
    } else {
        gsrc  = (const char*)(g_coresT + (size_t)(NSITES - 1) * 50); // site 781 desc
        gstep = -800;
        fp    = g_feat + (size_t)(NQ - 2) * BQ + b;
        fstep = -(long)BQ;
    }

    const uint32_t sbase = (uint32_t)__cvta_generic_to_shared(&smem[wid][0][0]);

    // prologue: stage quads 0,1 (sites 0..7), one commit group per quad
    {
        const char* g = gsrc;
        #pragma unroll
        for (int q = 0; q < 2; q++) {
            #pragma unroll
            for (int s = 0; s < 4; s++) {
                stage_site(sbase + (4 * q + s) * 800, g, lane);
                g += gstep;
            }
            cp_commit();
        }
    }
    const char* gstage = gsrc + 8 * gstep;     // next site to stage (site 8)

    // init state
    ull vp[5];
    if (fwd) {
        const float2 f0 = g_feat[b];
        const ull* cfc = (const ull*)core_first;
        const ull* cfs = (const ull*)(core_first + 10);
        const ull c02 = pack2(f0.x, f0.x);
        const ull s02 = pack2(f0.y, f0.y);
        #pragma unroll
        for (int j = 0; j < 5; j++)
            vp[j] = fma2(s02, __ldg(cfs + j), mul2(c02, __ldg(cfc + j)));
    } else {
        const float2 fL = g_feat[(size_t)(NQ - 1) * BQ + b];
        const float2* cl = (const float2*)core_last;
        #pragma unroll
        for (int j = 0; j < 5; j++) {
            float2 qa = __ldg(cl + 2 * j);
            float2 qb = __ldg(cl + 2 * j + 1);
            vp[j] = pack2(fL.x * qa.x + fL.y * qa.y,
                          fL.x * qb.x + fL.y * qb.y);
        }
    }

    // feature regs for current quad; prefetch pointer for next quad
    float2 fc0 = fp[0];
    float2 fc1 = fp[fstep];
    float2 fc2 = fp[2 * fstep];
    float2 fc3 = fp[3 * fstep];
    const float2* fpre = fp + 4 * fstep;

    int slot = 0;   // smem slot (site units) of current quad: 0,4,8,0,...

    for (int q = 0; q < NQUAD; q++) {
        cp_wait<1>();               // current quad staged
        __syncwarp();

        // prefetch next quad's features
        const float2 fn0 = fpre[0];
        const float2 fn1 = fpre[fstep];
        const float2 fn2 = fpre[2 * fstep];
        const float2 fn3 = fpre[3 * fstep];
        fpre += 4 * fstep;

        const char* base = &smem[wid][slot][0];
        chain_step((const ulonglong2*)base, fc0, vp);
        chain_step((const ulonglong2*)(base + 800), fc1, vp);
        chain_step((const ulonglong2*)(base + 1600), fc2, vp);
        chain_step((const ulonglong2*)(base + 2400), fc3, vp);
        fc0 = fn0; fc1 = fn1; fc2 = fn2; fc3 = fn3;

        // stage quad q+2 (sites 4q+8..11) — unconditional, always in-bounds
        int wslot = slot + 8; if (wslot >= RING) wslot -= RING;
        uint32_t dst = sbase + wslot * 800;
        #pragma unroll
        for (int s = 0; s < 4; s++) {
            stage_site(dst + s * 800, gstage, lane);
            gstage += gstep;
        }
        cp_commit();

        slot += 4; if (slot >= RING) slot -= RING;
    }

    // remainder: sites 388,389,390 (quad 97, staged at 'slot')
    cp_wait<0>();
    __syncwarp();
    {
        const char* base = &smem[wid][slot][0];
        chain_step((const ulonglong2*)base, fc0, vp);
        chain_step((const ulonglong2*)(base + 800), fc1, vp);
        chain_step((const ulonglong2*)(base + 1600), fc2, vp);
    }

    if (fwd) {
        #pragma unroll
        for (int j = 0; j < 5; j++) g_V[(size_t)j * BQ + b] = vp[j];
    } else {
        #pragma unroll
        for (int j = 0; j < 5; j++) g_U[(size_t)j * BQ + b] = vp[j];
    }
}

// ---------------------------------------------------------------------------
// K3: s[b] = dot(v,u);  logits[b,c] = s[b] * w[c],  w[c] = sum_d OT[c,d,0]
// g_V/g_U in [j][b] layout -> fully coalesced loads.
// ---------------------------------------------------------------------------
__global__ void combine_kernel(const float* __restrict__ ot,
                               float* __restrict__ out) {
    __shared__ float ws[10];
    const int tid = threadIdx.x;
    if (tid < 10) {
        float w = 0.f;
        #pragma unroll
        for (int d = 0; d < 10; d++) w += ot[tid * 10 + d];
        ws[tid] = w;
    }
    __syncthreads();

    const int b = blockIdx.x * blockDim.x + tid;
    if (b >= BQ) return;
    float s = 0.f;
    #pragma unroll
    for (int j = 0; j < 5; j++) {
        float2 a = unpack2(g_V[(size_t)j * BQ + b]);
        float2 u = unpack2(g_U[(size_t)j * BQ + b]);
        s += a.x * u.x + a.y * u.y;
    }
    #pragma unroll
    for (int c = 0; c < 10; c++)
        out[(size_t)b * 10 + c] = s * ws[c];
}

// ---------------------------------------------------------------------------
extern "C" void kernel_launch(void* const* d_in, const int* in_sizes, int n_in,
                              void* d_out, int out_size) {
    const float* x          = (const float*)d_in[0];  // (8192, 784)
    const float* core_first = (const float*)d_in[1];  // (1, 2, 10)
    const float* cores_mid  = (const float*)d_in[2];  // (782, 10, 2, 10)
    const float* core_last  = (const float*)d_in[3];  // (10, 2, 1)
    const float* out_t      = (const float*)d_in[4];  // (10, 10, 1)
    float* out = (float*)d_out;                       // (8192, 10)

    dim3 fgrid((NQ + 31) / 32, BQ / 32);
    dim3 fblk(32, 8);
    feat_kernel<<<fgrid, fblk>>>(x);
    transpose_cores<<<NSITES, 200>>>(cores_mid);

    chain_kernel<<<128, 128>>>(core_first, cores_mid, core_last);

    combine_kernel<<<BQ / 128, 128>>>(out_t, out);
}